// round 16
// baseline (speedup 1.0000x reference)
#include <cuda_runtime.h>
#include <cstdint>

#define N_BITS 108
#define N_OUT  7
#define TPB    256
#define NWARPS (TPB / 32)

// Row = 108 floats = 432 B = 27 uint4. Values exactly 0.0f/1.0f:
// (word >> 29) & 1 extracts the bit. Row DRAM phase mod 32 = 16*(row&1).
//
// Sector-exact two-phase scan:
//   Head:  even rows words 0..7 (bits [0,32)), odd rows words 0..6 ([0,28))
//          -> always exactly sectors 0..3 of the row span (128 B).
//   Drain: queued rows (38%), words (8-(row&1)) .. 26 -> exactly sectors
//          4..13 (320 B), disjoint from head, fully sector-aligned.
// Drain = 1 row per warp per iteration (lanes 0..18/19 load 304/320 B
// contiguous), software-pipelined one iteration ahead (R15-proven mechanics).

__device__ __forceinline__ unsigned mask4(uint4 w) {
    return ((w.x >> 29) & 1u)
         | (((w.y >> 29) & 1u) << 1)
         | (((w.z >> 29) & 1u) << 2)
         | (((w.w >> 29) & 1u) << 3);
}

__global__ __launch_bounds__(TPB, 8)
void lzd108_kernel(const uint4* __restrict__ X, float* __restrict__ out, int n_rows) {
    __shared__ unsigned short s_pos[TPB];
    __shared__ unsigned short s_q[TPB];
    __shared__ int s_cnt;

    int tid = threadIdx.x;
    if (tid == 0) s_cnt = 0;
    __syncthreads();

    size_t brow = (size_t)blockIdx.x * TPB;
    int row = (int)brow + tid;
    int pos = N_BITS;  // 108 = 1101100b == LZC_108 (all-zero row)

    if (row < n_rows) {
        const uint4* p = X + (size_t)row * 27;
        int oddr = row & 1;

        // Head: words 0..6 always; word 7 only for even rows (sector-exact).
        unsigned m = 0;
        #pragma unroll
        for (int j = 0; j < 7; ++j) m |= mask4(__ldg(p + j)) << (4 * j);
        if (!oddr) m |= mask4(__ldg(p + 7)) << 28;
        if (m) pos = __ffs(m) - 1;
        else   s_q[atomicAdd(&s_cnt, 1)] = (unsigned short)tid;
    }
    s_pos[tid] = (unsigned short)pos;
    __syncthreads();

    // Drain: 1 row per warp per iteration, pipelined one ahead.
    {
        int nq = s_cnt;
        int lane = tid & 31;
        int wid = tid >> 5;

        int it = wid;
        int t = -1;
        unsigned mym = 0;
        if (it < nq) {
            t = s_q[it];
            int ws = 8 - (t & 1);               // first drain word
            int nw = 19 + (t & 1);              // word count (19 even / 20 odd)
            if (lane < nw)
                mym = mask4(__ldg(X + (brow + (size_t)t) * 27 + ws + lane));
        }
        while (it < nq) {
            int nit = it + NWARPS;
            int nt = -1;
            unsigned nm = 0;
            if (nit < nq) {                      // prefetch next iteration
                nt = s_q[nit];
                int ws = 8 - (nt & 1);
                int nw = 19 + (nt & 1);
                if (lane < nw)
                    nm = mask4(__ldg(X + (brow + (size_t)nt) * 27 + ws + lane));
            }
            unsigned bal = __ballot_sync(0xFFFFFFFFu, mym != 0u);
            if (bal) {
                int fl = __ffs(bal) - 1;         // first lane with a hit
                unsigned wm = __shfl_sync(0xFFFFFFFFu, mym, fl);
                if (lane == 0) {
                    int ws = 8 - (t & 1);
                    s_pos[t] = (unsigned short)(4 * (ws + fl) + __ffs(wm) - 1);
                }
            }
            // ballot 0 -> all-zero past head, stays 108
            it = nit; t = nt; mym = nm;
        }
    }
    __syncthreads();

    // Coalesced output: block writes its 1792 floats contiguously.
    size_t ob = brow * N_OUT;
    size_t total = (size_t)n_rows * N_OUT;
    #pragma unroll
    for (int i = 0; i < N_OUT; ++i) {
        size_t gi = ob + (size_t)(i * TPB + tid);
        if (gi < total) {
            int local = i * TPB + tid;   // 0..1791
            int r = local / N_OUT;
            int b = local - r * N_OUT;
            out[gi] = (float)((s_pos[r] >> (6 - b)) & 1);
        }
    }
}

extern "C" void kernel_launch(void* const* d_in, const int* in_sizes, int n_in,
                              void* d_out, int out_size) {
    const uint4* X = (const uint4*)d_in[0];
    float* out = (float*)d_out;
    int n_rows = in_sizes[0] / N_BITS;

    int blocks = (n_rows + TPB - 1) / TPB;
    lzd108_kernel<<<blocks, TPB>>>(X, out, n_rows);
}

// round 17
// speedup vs baseline: 1.0042x; 1.0042x over previous
#include <cuda_runtime.h>
#include <cstdint>

#define N_BITS 108
#define N_OUT  7
#define TPB    256
#define NWARPS (TPB / 32)

// Row = 108 floats = 432 B = 27 uint4. Values exactly 0.0f/1.0f:
// (word >> 29) & 1 extracts the bit.
// R7 champion structure, UNCHANGED byte pattern (594 MB measured), with the
// drain software-pipelined one iteration ahead to hide its serialized
// load->ballot latency (the only exposed-latency part of R7).
// Phase 1: row-per-thread head, words 0..7 (128 B) -> resolves 62%.
// Phase 2: queued rows, words 8..26 (304 B) — 2 rows per warp iteration
// (16-lane groups, lanes li<11... li indexes 19 words via li<19 split below),
// prefetched one iteration deep.

__device__ __forceinline__ unsigned mask4(uint4 w) {
    return ((w.x >> 29) & 1u)
         | (((w.y >> 29) & 1u) << 1)
         | (((w.z >> 29) & 1u) << 2)
         | (((w.w >> 29) & 1u) << 3);
}

__global__ __launch_bounds__(TPB, 8)
void lzd108_kernel(const uint4* __restrict__ X, float* __restrict__ out, int n_rows) {
    __shared__ unsigned short s_pos[TPB];
    __shared__ unsigned short s_q[TPB];
    __shared__ int s_cnt;

    int tid = threadIdx.x;
    if (tid == 0) s_cnt = 0;
    __syncthreads();

    size_t brow = (size_t)blockIdx.x * TPB;
    int row = (int)brow + tid;
    int pos = N_BITS;  // 108 = 1101100b == LZC_108 (all-zero row)

    if (row < n_rows) {
        const uint4* p = X + (size_t)row * 27;
        // Phase 1: bits [0,32) — words 0..7, 8 independent LDG.128
        unsigned m = 0;
        #pragma unroll
        for (int j = 0; j < 8; ++j) m |= mask4(__ldg(p + j)) << (4 * j);
        if (m) pos = __ffs(m) - 1;
        else   s_q[atomicAdd(&s_cnt, 1)] = (unsigned short)tid;
    }
    s_pos[tid] = (unsigned short)pos;
    __syncthreads();

    // Phase 2: drain — bits [32,108) = words 8..26 (19 uint4), one row per
    // warp iteration (lanes 0..18 load 304 B contiguous), PIPELINED: while
    // resolving iteration i, iteration i+1's loads are already in flight.
    // NOTE: identical global byte pattern to R7; only scheduling differs.
    {
        int nq = s_cnt;
        int lane = tid & 31;
        int wid = tid >> 5;
        int g = lane >> 4;          // 0/1: two rows per iteration
        int li = lane & 15;         // word li within the row (active li<19? no: li<11 for hi half)
        // Row g covers words 8+g*0 .. — we need 19 words with 16 lanes, so use
        // R7's exact split: lanes 0-15 -> row A words 8..23 is 16 words, but
        // R7 used li<11 over words 16..26. To keep R7's BYTE pattern (words
        // 8..26 per queued row) with 2 rows/iter and 32 lanes, give each row
        // 16 lanes loading words 8..23 (li<16) and let lanes 0..2 of the OTHER
        // half also load words 24..26. Simpler correct variant: one row per
        // 32-lane warp but TWO iterations in flight (double prefetch).
        (void)g; (void)li;

        int it = wid;
        // stage A (current) and stage B (next) in flight simultaneously
        int tA = -1; unsigned mA = 0;
        if (it < nq) {
            tA = s_q[it];
            if (lane < 19) mA = mask4(__ldg(X + (brow + (size_t)tA) * 27 + 8 + lane));
        }
        int itB = it + NWARPS;
        int tB = -1; unsigned mB = 0;
        if (itB < nq) {
            tB = s_q[itB];
            if (lane < 19) mB = mask4(__ldg(X + (brow + (size_t)tB) * 27 + 8 + lane));
        }
        while (it < nq) {
            // prefetch iteration i+2 before resolving i
            int itC = itB + NWARPS;
            int tC = -1; unsigned mC = 0;
            if (itC < nq) {
                tC = s_q[itC];
                if (lane < 19) mC = mask4(__ldg(X + (brow + (size_t)tC) * 27 + 8 + lane));
            }
            unsigned bal = __ballot_sync(0xFFFFFFFFu, mA != 0u);
            if (bal) {
                int fl = __ffs(bal) - 1;
                unsigned wm = __shfl_sync(0xFFFFFFFFu, mA, fl);
                if (lane == 0)
                    s_pos[tA] = (unsigned short)(32 + 4 * fl + __ffs(wm) - 1);
            }
            // ballot 0 -> all-zero past head, stays 108
            it = itB; tA = tB; mA = mB;
            itB = itC; tB = tC; mB = mC;
        }
    }
    __syncthreads();

    // Coalesced output: block writes its 1792 floats contiguously.
    size_t ob = brow * N_OUT;
    size_t total = (size_t)n_rows * N_OUT;
    #pragma unroll
    for (int i = 0; i < N_OUT; ++i) {
        size_t gi = ob + (size_t)(i * TPB + tid);
        if (gi < total) {
            int local = i * TPB + tid;   // 0..1791
            int r = local / N_OUT;
            int b = local - r * N_OUT;
            out[gi] = (float)((s_pos[r] >> (6 - b)) & 1);
        }
    }
}

extern "C" void kernel_launch(void* const* d_in, const int* in_sizes, int n_in,
                              void* d_out, int out_size) {
    const uint4* X = (const uint4*)d_in[0];
    float* out = (float*)d_out;
    int n_rows = in_sizes[0] / N_BITS;

    int blocks = (n_rows + TPB - 1) / TPB;
    lzd108_kernel<<<blocks, TPB>>>(X, out, n_rows);
}